// round 7
// baseline (speedup 1.0000x reference)
#include <cuda_runtime.h>

// out[b, i] = cos(q_weights[i]) * (sum_k sign_i(k) * x[b,k]^2) / (sum_k x[b,k]^2)
// Analytic collapse: RX^dag Z RX = cos(t) Z + sin(t) Y, and <Y> = 0 for the real
// embedded state, so the circuit is cos(theta_i) * classical Z-expectation.
//
// R7: R4's memory body (512 thr x 4096 blk, 25.57us = 6.26 TB/s, roofline) with
// the cosf/smem/__syncthreads block prologue hoisted into a separate 1-thread
// kernel writing a __device__ float4. Main kernel reads it with one broadcast
// __ldg that overlaps the data loads — no barrier on the block-startup
// critical path.

__device__ float4 g_cq;

__global__ void compute_cq_kernel(const float* __restrict__ qw) {
    g_cq = make_float4(cosf(qw[0]), cosf(qw[1]), cosf(qw[2]), cosf(qw[3]));
}

__global__ __launch_bounds__(512) void quantum_layer_kernel(
    const float4* __restrict__ x,     // [B*4] float4 = [B,16] floats
    float4*       __restrict__ out,   // [B] float4 = [B,4] floats
    int B)
{
    int i = blockIdx.x * blockDim.x + threadIdx.x;
    if (i >= B) return;

    const float4* p = x + (size_t)i * 4;
    float4 g0 = __ldcs(p + 0);
    float4 g1 = __ldcs(p + 1);
    float4 g2 = __ldcs(p + 2);
    float4 g3 = __ldcs(p + 3);
    float4 cq = __ldg(&g_cq);          // broadcast, overlaps data loads

    float a0 = g0.x * g0.x, a1 = g0.y * g0.y, a2 = g0.z * g0.z, a3 = g0.w * g0.w;
    float b0 = g1.x * g1.x, b1 = g1.y * g1.y, b2 = g1.z * g1.z, b3 = g1.w * g1.w;
    float c0 = g2.x * g2.x, c1 = g2.y * g2.y, c2 = g2.z * g2.z, c3 = g2.w * g2.w;
    float d0 = g3.x * g3.x, d1 = g3.y * g3.y, d2 = g3.z * g3.z, d3 = g3.w * g3.w;

    float sA = a0 + a1 + a2 + a3;               // group 0 (k=0..3)
    float sB = b0 + b1 + b2 + b3;               // group 1 (k=4..7)
    float sC = c0 + c1 + c2 + c3;               // group 2 (k=8..11)
    float sD = d0 + d1 + d2 + d3;               // group 3 (k=12..15)

    float p0A = (a0 + a2) - (a1 + a3);          // LSB sign within group
    float p0B = (b0 + b2) - (b1 + b3);
    float p0C = (c0 + c2) - (c1 + c3);
    float p0D = (d0 + d2) - (d1 + d3);

    float p1A = (a0 + a1) - (a2 + a3);          // bit1 sign within group
    float p1B = (b0 + b1) - (b2 + b3);
    float p1C = (c0 + c1) - (c2 + c3);
    float p1D = (d0 + d1) - (d2 + d3);

    float norm = (sA + sB) + (sC + sD);

    float z0 = (sA + sB) - (sC + sD);           // wire 0 (MSB of k)
    float z1 = (sA - sB) + (sC - sD);           // wire 1
    float z2 = (p1A + p1B) + (p1C + p1D);       // wire 2
    float z3 = (p0A + p0B) + (p0C + p0D);       // wire 3 (LSB of k)

    float inv = 1.0f / norm;

    float4 r;
    r.x = cq.x * z0 * inv;
    r.y = cq.y * z1 * inv;
    r.z = cq.z * z2 * inv;
    r.w = cq.w * z3 * inv;
    __stcs(out + i, r);
}

extern "C" void kernel_launch(void* const* d_in, const int* in_sizes, int n_in,
                              void* d_out, int out_size) {
    const float* x  = (const float*)d_in[0];
    const float* qw = (const float*)d_in[1];
    float* out = (float*)d_out;

    int B = in_sizes[0] / 16;   // 2097152

    compute_cq_kernel<<<1, 1>>>(qw);

    int threads = 512;
    int blocks = (B + threads - 1) / threads;   // 4096
    quantum_layer_kernel<<<blocks, threads>>>(
        (const float4*)x, (float4*)out, B);
}

// round 8
// speedup vs baseline: 1.2054x; 1.2054x over previous
#include <cuda_runtime.h>

// out[b, i] = cos(q_weights[i]) * (sum_k sign_i(k) * x[b,k]^2) / (sum_k x[b,k]^2)
// Analytic collapse: RX^dag Z RX = cos(t) Z + sin(t) Y, and <Y> = 0 for the real
// embedded state, so the circuit is cos(theta_i) * classical Z-expectation.
//
// R8 (final): R4's winning config — single launch, 512 threads x 4096 blocks,
// smem-cached cosines, streaming cache hints — with the bounds guard removed
// (B = 4096*512 exactly; guarded fallback kept for other shapes). Kernel is at
// the streaming-memory roofline: 160 MB compulsory traffic @ ~6.26 TB/s
// effective; R5/R7 established that layout changes and launch splitting only
// regress from here.

__global__ __launch_bounds__(512) void quantum_layer_kernel(
    const float4* __restrict__ x,     // [B*4] float4 = [B,16] floats
    const float*  __restrict__ qw,    // [4]
    float4*       __restrict__ out)   // [B] float4 = [B,4] floats
{
    __shared__ float cq[4];
    if (threadIdx.x < 4) cq[threadIdx.x] = cosf(qw[threadIdx.x]);
    __syncthreads();

    int i = blockIdx.x * blockDim.x + threadIdx.x;

    const float4* p = x + (size_t)i * 4;
    float4 g0 = __ldcs(p + 0);
    float4 g1 = __ldcs(p + 1);
    float4 g2 = __ldcs(p + 2);
    float4 g3 = __ldcs(p + 3);

    float a0 = g0.x * g0.x, a1 = g0.y * g0.y, a2 = g0.z * g0.z, a3 = g0.w * g0.w;
    float b0 = g1.x * g1.x, b1 = g1.y * g1.y, b2 = g1.z * g1.z, b3 = g1.w * g1.w;
    float c0 = g2.x * g2.x, c1 = g2.y * g2.y, c2 = g2.z * g2.z, c3 = g2.w * g2.w;
    float d0 = g3.x * g3.x, d1 = g3.y * g3.y, d2 = g3.z * g3.z, d3 = g3.w * g3.w;

    float sA = a0 + a1 + a2 + a3;               // group 0 (k=0..3)
    float sB = b0 + b1 + b2 + b3;               // group 1 (k=4..7)
    float sC = c0 + c1 + c2 + c3;               // group 2 (k=8..11)
    float sD = d0 + d1 + d2 + d3;               // group 3 (k=12..15)

    float p0A = (a0 + a2) - (a1 + a3);          // LSB sign within group
    float p0B = (b0 + b2) - (b1 + b3);
    float p0C = (c0 + c2) - (c1 + c3);
    float p0D = (d0 + d2) - (d1 + d3);

    float p1A = (a0 + a1) - (a2 + a3);          // bit1 sign within group
    float p1B = (b0 + b1) - (b2 + b3);
    float p1C = (c0 + c1) - (c2 + c3);
    float p1D = (d0 + d1) - (d2 + d3);

    float norm = (sA + sB) + (sC + sD);

    float z0 = (sA + sB) - (sC + sD);           // wire 0 (MSB of k)
    float z1 = (sA - sB) + (sC - sD);           // wire 1
    float z2 = (p1A + p1B) + (p1C + p1D);       // wire 2
    float z3 = (p0A + p0B) + (p0C + p0D);       // wire 3 (LSB of k)

    float inv = 1.0f / norm;

    float4 r;
    r.x = cq[0] * z0 * inv;
    r.y = cq[1] * z1 * inv;
    r.z = cq[2] * z2 * inv;
    r.w = cq[3] * z3 * inv;
    __stcs(out + i, r);
}

// Guarded fallback for shapes not divisible by the block size.
__global__ __launch_bounds__(512) void quantum_layer_kernel_guard(
    const float4* __restrict__ x,
    const float*  __restrict__ qw,
    float4*       __restrict__ out,
    int B)
{
    __shared__ float cq[4];
    if (threadIdx.x < 4) cq[threadIdx.x] = cosf(qw[threadIdx.x]);
    __syncthreads();

    int i = blockIdx.x * blockDim.x + threadIdx.x;
    if (i >= B) return;

    const float4* p = x + (size_t)i * 4;
    float4 g0 = __ldcs(p + 0);
    float4 g1 = __ldcs(p + 1);
    float4 g2 = __ldcs(p + 2);
    float4 g3 = __ldcs(p + 3);

    float a0 = g0.x * g0.x, a1 = g0.y * g0.y, a2 = g0.z * g0.z, a3 = g0.w * g0.w;
    float b0 = g1.x * g1.x, b1 = g1.y * g1.y, b2 = g1.z * g1.z, b3 = g1.w * g1.w;
    float c0 = g2.x * g2.x, c1 = g2.y * g2.y, c2 = g2.z * g2.z, c3 = g2.w * g2.w;
    float d0 = g3.x * g3.x, d1 = g3.y * g3.y, d2 = g3.z * g3.z, d3 = g3.w * g3.w;

    float sA = a0 + a1 + a2 + a3;
    float sB = b0 + b1 + b2 + b3;
    float sC = c0 + c1 + c2 + c3;
    float sD = d0 + d1 + d2 + d3;

    float p0A = (a0 + a2) - (a1 + a3);
    float p0B = (b0 + b2) - (b1 + b3);
    float p0C = (c0 + c2) - (c1 + c3);
    float p0D = (d0 + d2) - (d1 + d3);

    float p1A = (a0 + a1) - (a2 + a3);
    float p1B = (b0 + b1) - (b2 + b3);
    float p1C = (c0 + c1) - (c2 + c3);
    float p1D = (d0 + d1) - (d2 + d3);

    float norm = (sA + sB) + (sC + sD);
    float z0 = (sA + sB) - (sC + sD);
    float z1 = (sA - sB) + (sC - sD);
    float z2 = (p1A + p1B) + (p1C + p1D);
    float z3 = (p0A + p0B) + (p0C + p0D);

    float inv = 1.0f / norm;

    float4 r;
    r.x = cq[0] * z0 * inv;
    r.y = cq[1] * z1 * inv;
    r.z = cq[2] * z2 * inv;
    r.w = cq[3] * z3 * inv;
    __stcs(out + i, r);
}

extern "C" void kernel_launch(void* const* d_in, const int* in_sizes, int n_in,
                              void* d_out, int out_size) {
    const float* x  = (const float*)d_in[0];
    const float* qw = (const float*)d_in[1];
    float* out = (float*)d_out;

    int B = in_sizes[0] / 16;   // 2097152
    int threads = 512;
    if (B % threads == 0) {
        quantum_layer_kernel<<<B / threads, threads>>>(
            (const float4*)x, qw, (float4*)out);
    } else {
        quantum_layer_kernel_guard<<<(B + threads - 1) / threads, threads>>>(
            (const float4*)x, qw, (float4*)out, B);
    }
}